// round 5
// baseline (speedup 1.0000x reference)
#include <cuda_runtime.h>
#include <cuda_bf16.h>
#include <cstdint>

// Problem constants (match reference setup_inputs)
#define N_NODES 100000
#define N_EDGES 600000
#define IN_DIM  128
#define OUT_DIM 64

// -------- device-global scratch (no allocations allowed) --------
// Declared as float4 to guarantee 16B alignment for vector loads / red.v4.
__device__ float4 g_t1_v[(size_t)N_NODES * IN_DIM / 4];    // x @ W1           (51.2 MB)
__device__ float4 g_agg1_v[(size_t)N_NODES * IN_DIM / 4];  // spmm-1 acc       (51.2 MB)
__device__ float4 g_t2_v[(size_t)N_NODES * OUT_DIM / 4];   // h @ W2           (25.6 MB)
__device__ int    g_src[N_EDGES];                          // decoded edge src (2.4 MB)
__device__ int    g_dst[N_EDGES];                          // decoded edge dst (2.4 MB)

// -------- edge-index decode: auto-detect int32 vs int64 --------
// int32 data reinterpreted as int64 has a (almost surely) nonzero high word
// or out-of-range value among the first 4 entries.
__device__ __forceinline__ bool ei_is_int64(const void* p) {
    const long long* q = (const long long*)p;
    #pragma unroll
    for (int i = 0; i < 4; i++) {
        long long v = q[i];
        if (v < 0 || v >= N_NODES) return false;
    }
    return true;
}

__global__ __launch_bounds__(256) void decode_edges(const void* __restrict__ ei, int E) {
    int e = blockIdx.x * blockDim.x + threadIdx.x;
    if (e >= E) return;
    long long s, d;
    if (ei_is_int64(ei)) {
        const long long* q = (const long long*)ei;
        s = q[e]; d = q[(size_t)E + e];
    } else {
        const int* q = (const int*)ei;
        s = q[e]; d = q[(size_t)E + e];
    }
    // defensive clamp (avoids OOB crash if detection ever mis-fires)
    if (s < 0 || s >= N_NODES) s = 0;
    if (d < 0 || d >= N_NODES) d = 0;
    g_src[e] = (int)s;
    g_dst[e] = (int)d;
}

// -------- zero the layer-1 accumulator --------
__global__ __launch_bounds__(256) void zero_agg1() {
    size_t i = (size_t)blockIdx.x * blockDim.x + threadIdx.x;
    size_t n4 = (size_t)N_NODES * IN_DIM / 4;
    if (i < n4) g_agg1_v[i] = make_float4(0.f, 0.f, 0.f, 0.f);
}

// -------- out[n][d] = b2[d]  (accumulator init for layer-2 spmm) --------
__global__ __launch_bounds__(256) void init_out(float* __restrict__ out,
                                                const float* __restrict__ b2) {
    size_t i = (size_t)blockIdx.x * blockDim.x + threadIdx.x;
    if (i < (size_t)N_NODES * OUT_DIM) {
        out[i] = b2[i & (OUT_DIM - 1)];
    }
}

// -------- tiled SGEMM: C[M, OD] = A'[M,128] @ W[128, OD] --------
// A' = A (plain) or relu(A + bias) when FUSE_RELU_BIAS (bias indexed by k).
// Tile: 64 rows x OD cols, K-step 16, 256 threads, thread tile 4 x (OD/16).
template<int OD, bool FUSE_RELU_BIAS>
__global__ __launch_bounds__(256) void gemm_k128(const float* __restrict__ A,
                                                 const float* __restrict__ W,
                                                 const float* __restrict__ bias,
                                                 float* __restrict__ C,
                                                 int M) {
    constexpr int BM = 64;
    constexpr int KS = 16;
    constexpr int TN = OD / 16;   // 8 (OD=128) or 4 (OD=64)

    __shared__ float sA[KS][BM];          // transposed A tile
    __shared__ float sW[KS * OD];         // W tile (contiguous rows)

    const int block_row = blockIdx.x * BM;
    const int t  = threadIdx.x;           // 0..255
    const int tx = t & 15;                // output col group
    const int ty = t >> 4;                // output row group (0..15)

    float acc[4][TN];
    #pragma unroll
    for (int i = 0; i < 4; i++)
        #pragma unroll
        for (int j = 0; j < TN; j++) acc[i][j] = 0.f;

    for (int k0 = 0; k0 < 128; k0 += KS) {
        // --- load A tile (64 x 16) transposed into sA[k][row] ---
        {
            const int kk = t & (KS - 1);       // 0..15
            const int r0 = (t >> 4) * 4;       // 0,4,...,60
            #pragma unroll
            for (int i = 0; i < 4; i++) {
                const int r = r0 + i;
                const int grow = block_row + r;
                float v = 0.f;
                if (grow < M) {
                    v = A[(size_t)grow * 128 + k0 + kk];
                    if (FUSE_RELU_BIAS) v = fmaxf(v + __ldg(&bias[k0 + kk]), 0.f);
                }
                sA[kk][r] = v;
            }
        }
        // --- load W tile (16 x OD, contiguous) ---
        {
            const float* Wp = W + (size_t)k0 * OD;
            #pragma unroll
            for (int i = 0; i < KS * OD / 256; i++)
                sW[t + 256 * i] = Wp[t + 256 * i];
        }
        __syncthreads();

        #pragma unroll
        for (int k = 0; k < KS; k++) {
            const float4 a4 = *(const float4*)&sA[k][ty * 4];
            const float av[4] = {a4.x, a4.y, a4.z, a4.w};
            float bv[TN];
            #pragma unroll
            for (int j = 0; j < TN; j += 4) {
                const float4 b4 = *(const float4*)&sW[k * OD + tx * TN + j];
                bv[j + 0] = b4.x; bv[j + 1] = b4.y; bv[j + 2] = b4.z; bv[j + 3] = b4.w;
            }
            #pragma unroll
            for (int i = 0; i < 4; i++)
                #pragma unroll
                for (int j = 0; j < TN; j++)
                    acc[i][j] += av[i] * bv[j];
        }
        __syncthreads();
    }

    // --- store (vectorized float4) ---
    #pragma unroll
    for (int i = 0; i < 4; i++) {
        const int grow = block_row + ty * 4 + i;
        if (grow < M) {
            float4* cp = (float4*)&C[(size_t)grow * OD + tx * TN];
            #pragma unroll
            for (int j = 0; j < TN / 4; j++) {
                cp[j] = make_float4(acc[i][4 * j + 0], acc[i][4 * j + 1],
                                    acc[i][4 * j + 2], acc[i][4 * j + 3]);
            }
        }
    }
}

// -------- SpMM scatter: acc[dst] += w_e * feat[src], D floats per edge --------
// One edge handled by D/4 threads, each does a float4 gather + vector red.add.
template<int D>
__global__ __launch_bounds__(256) void spmm_scatter(const float* __restrict__ ew,
                                                    const float* __restrict__ feat,
                                                    float* __restrict__ acc,
                                                    int E) {
    constexpr int L = D / 4;  // threads per edge: 32 (D=128) or 16 (D=64)
    const long long tid = (long long)blockIdx.x * blockDim.x + threadIdx.x;
    const int e = (int)(tid / L);
    const int lane = (int)(tid % L);
    if (e >= E) return;

    const int s = g_src[e];
    const int d = g_dst[e];
    const float w = ew[e];

    const float4 v = ((const float4*)(feat + (size_t)s * D))[lane];
    float4* p = ((float4*)(acc + (size_t)d * D)) + lane;

    asm volatile("red.global.add.v4.f32 [%0], {%1, %2, %3, %4};"
                 :: "l"(p), "f"(v.x * w), "f"(v.y * w), "f"(v.z * w), "f"(v.w * w)
                 : "memory");
}

extern "C" void kernel_launch(void* const* d_in, const int* in_sizes, int n_in,
                              void* d_out, int out_size) {
    // Identify inputs by element count (robust to metadata ordering):
    //   x: 12,800,000  edge_index: 1,200,000  edge_weight: 600,000
    //   W1: 16,384     b1: 128                W2: 8,192       b2: 64
    const float* x  = nullptr; const void* ei = nullptr; const float* ew = nullptr;
    const float* W1 = nullptr; const float* b1 = nullptr;
    const float* W2 = nullptr; const float* b2 = nullptr;
    for (int i = 0; i < n_in; i++) {
        switch (in_sizes[i]) {
            case 12800000: x  = (const float*)d_in[i]; break;
            case 1200000:  ei = d_in[i];               break;
            case 600000:   ew = (const float*)d_in[i]; break;
            case 16384:    W1 = (const float*)d_in[i]; break;
            case 128:      b1 = (const float*)d_in[i]; break;
            case 8192:     W2 = (const float*)d_in[i]; break;
            case 64:       b2 = (const float*)d_in[i]; break;
            default: break;
        }
    }
    float* out = (float*)d_out;

    const int M = N_NODES;
    const int E = N_EDGES;

    float* t1;   cudaGetSymbolAddress((void**)&t1,   g_t1_v);
    float* agg1; cudaGetSymbolAddress((void**)&agg1, g_agg1_v);
    float* t2;   cudaGetSymbolAddress((void**)&t2,   g_t2_v);

    // 0) decode edge indices (dtype autodetect) into compact int32 arrays
    decode_edges<<<(E + 255) / 256, 256>>>(ei, E);

    // 1) zero layer-1 accumulator
    {
        size_t n4 = (size_t)N_NODES * IN_DIM / 4;
        zero_agg1<<<(int)((n4 + 255) / 256), 256>>>();
    }
    // 2) t1 = x @ W1
    gemm_k128<IN_DIM, false><<<(M + 63) / 64, 256>>>(x, W1, nullptr, t1, M);

    // 3) agg1[dst] += w * t1[src]
    {
        long long threads = (long long)E * (IN_DIM / 4);
        spmm_scatter<IN_DIM><<<(int)((threads + 255) / 256), 256>>>(ew, t1, agg1, E);
    }
    // 4) t2 = relu(agg1 + b1) @ W2
    gemm_k128<OUT_DIM, true><<<(M + 63) / 64, 256>>>(agg1, W2, b1, t2, M);

    // 5) out = b2 (broadcast init)
    {
        size_t n = (size_t)N_NODES * OUT_DIM;
        init_out<<<(int)((n + 255) / 256), 256>>>(out, b2);
    }
    // 6) out[dst] += w * t2[src]
    {
        long long threads = (long long)E * (OUT_DIM / 4);
        spmm_scatter<OUT_DIM><<<(int)((threads + 255) / 256), 256>>>(ew, t2, out, E);
    }
}

// round 6
// speedup vs baseline: 1.2945x; 1.2945x over previous
#include <cuda_runtime.h>
#include <cuda_bf16.h>
#include <mma.h>
#include <cstdint>

using namespace nvcuda;

// Problem constants (match reference setup_inputs)
#define N_NODES 100000
#define N_EDGES 600000
#define IN_DIM  128
#define OUT_DIM 64
#define PAD_ROWS 128   // tile padding so the fused GEMM needs no row predication

// -------- device-global scratch (no allocations allowed) --------
// float4 type guarantees 16B alignment for vector loads / red.v4.
__device__ float4 g_aggx_v[(size_t)(N_NODES + PAD_ROWS) * IN_DIM / 4];  // A @ x
__device__ float4 g_t2_v[(size_t)(N_NODES + PAD_ROWS) * OUT_DIM / 4];   // relu(..)@W2
__device__ int    g_src[N_EDGES];
__device__ int    g_dst[N_EDGES];

// -------- edge-index decode: auto-detect int32 vs int64 --------
__device__ __forceinline__ bool ei_is_int64(const void* p) {
    const long long* q = (const long long*)p;
    #pragma unroll
    for (int i = 0; i < 4; i++) {
        long long v = q[i];
        if (v < 0 || v >= N_NODES) return false;
    }
    return true;
}

__global__ __launch_bounds__(256) void decode_edges(const void* __restrict__ ei, int E) {
    int e = blockIdx.x * blockDim.x + threadIdx.x;
    if (e >= E) return;
    long long s, d;
    if (ei_is_int64(ei)) {
        const long long* q = (const long long*)ei;
        s = q[e]; d = q[(size_t)E + e];
    } else {
        const int* q = (const int*)ei;
        s = q[e]; d = q[(size_t)E + e];
    }
    if (s < 0 || s >= N_NODES) s = 0;
    if (d < 0 || d >= N_NODES) d = 0;
    g_src[e] = (int)s;
    g_dst[e] = (int)d;
}

// -------- zero the spmm-1 accumulator (incl. padding) --------
__global__ __launch_bounds__(256) void zero_aggx() {
    size_t i = (size_t)blockIdx.x * blockDim.x + threadIdx.x;
    size_t n4 = (size_t)(N_NODES + PAD_ROWS) * IN_DIM / 4;
    if (i < n4) g_aggx_v[i] = make_float4(0.f, 0.f, 0.f, 0.f);
}

// -------- out[n][d] = b2[d]  (accumulator init for layer-2 spmm) --------
__global__ __launch_bounds__(256) void init_out(float* __restrict__ out,
                                                const float* __restrict__ b2) {
    size_t i = (size_t)blockIdx.x * blockDim.x + threadIdx.x;
    if (i < (size_t)N_NODES * OUT_DIM) {
        out[i] = b2[i & (OUT_DIM - 1)];
    }
}

// -------- SpMM scatter: acc[dst] += w_e * feat[src], D floats per edge --------
template<int D>
__global__ __launch_bounds__(256) void spmm_scatter(const float* __restrict__ ew,
                                                    const float* __restrict__ feat,
                                                    float* __restrict__ acc,
                                                    int E) {
    constexpr int L = D / 4;  // threads per edge: 32 (D=128) or 16 (D=64)
    const long long tid = (long long)blockIdx.x * blockDim.x + threadIdx.x;
    const int e = (int)(tid / L);
    const int lane = (int)(tid % L);
    if (e >= E) return;

    const int s = g_src[e];
    const int d = g_dst[e];
    const float w = ew[e];

    const float4 v = __ldg(((const float4*)(feat + (size_t)s * D)) + lane);
    float4* p = ((float4*)(acc + (size_t)d * D)) + lane;

    asm volatile("red.global.add.v4.f32 [%0], {%1, %2, %3, %4};"
                 :: "l"(p), "f"(v.x * w), "f"(v.y * w), "f"(v.z * w), "f"(v.w * w)
                 : "memory");
}

// -------- fused tf32 tensor-core GEMM: t2 = relu(Aggx @ W1 + b1) @ W2 --------
// Block: 128 rows, 256 threads (8 warps). Each warp owns a 16-row strip.
// Stage 1: strip @ W1 (128x128, smem) -> smem C1 (+bias, relu, tf32-round).
// Stage 2: C1-strip @ W2 (128x64, smem) -> global t2.
// No cross-warp C1 dependency: each warp consumes only its own strip.
#define LDW1 136   // padded leading dims (16B multiples, bank-spread)
#define LDW2 72
#define LDC1 136

__global__ __launch_bounds__(256) void fused_gemm(const float* __restrict__ A,
                                                  const float* __restrict__ W1g,
                                                  const float* __restrict__ b1g,
                                                  const float* __restrict__ W2g,
                                                  float* __restrict__ t2) {
    extern __shared__ float smem[];
    float* sW1 = smem;                       // 128 x LDW1
    float* sW2 = sW1 + 128 * LDW1;           // 128 x LDW2
    float* sC1 = sW2 + 128 * LDW2;           // 128 x LDC1
    float* sB1 = sC1 + 128 * LDC1;           // 128

    const int t = threadIdx.x;

    // stage weights into smem, tf32-rounded
    for (int i = t; i < 128 * 128; i += 256) {
        sW1[(i >> 7) * LDW1 + (i & 127)] = wmma::__float_to_tf32(W1g[i]);
    }
    for (int i = t; i < 128 * 64; i += 256) {
        sW2[(i >> 6) * LDW2 + (i & 63)] = wmma::__float_to_tf32(W2g[i]);
    }
    if (t < 128) sB1[t] = b1g[t];
    __syncthreads();

    const int warp = t >> 5;
    const int lane = t & 31;
    const size_t row0 = (size_t)blockIdx.x * 128 + warp * 16;

    wmma::fragment<wmma::matrix_a, 16, 16, 8, wmma::precision::tf32, wmma::row_major> af;
    wmma::fragment<wmma::matrix_b, 16, 16, 8, wmma::precision::tf32, wmma::row_major> bf;

    // ---- stage 1: C1 = A_strip @ W1 ----
    {
        wmma::fragment<wmma::accumulator, 16, 16, 8, float> acc[8];
        #pragma unroll
        for (int n = 0; n < 8; n++) wmma::fill_fragment(acc[n], 0.f);

        #pragma unroll
        for (int k = 0; k < 16; k++) {
            wmma::load_matrix_sync(af, A + row0 * 128 + k * 8, 128);
            #pragma unroll
            for (int i = 0; i < af.num_elements; i++)
                af.x[i] = wmma::__float_to_tf32(af.x[i]);
            #pragma unroll
            for (int n = 0; n < 8; n++) {
                wmma::load_matrix_sync(bf, sW1 + (k * 8) * LDW1 + n * 16, LDW1);
                wmma::mma_sync(acc[n], af, bf, acc[n]);
            }
        }
        #pragma unroll
        for (int n = 0; n < 8; n++)
            wmma::store_matrix_sync(sC1 + warp * 16 * LDC1 + n * 16, acc[n],
                                    LDC1, wmma::mem_row_major);
    }
    __syncwarp();

    // ---- bias + relu + tf32-round on this warp's strip ----
    {
        float* base = sC1 + warp * 16 * LDC1;
        for (int i = lane; i < 16 * 32; i += 32) {  // 16 rows x 32 float4
            const int r = i >> 5;
            const int c4 = (i & 31) * 4;
            float4* p = (float4*)(base + r * LDC1 + c4);
            float4 v = *p;
            v.x = wmma::__float_to_tf32(fmaxf(v.x + sB1[c4 + 0], 0.f));
            v.y = wmma::__float_to_tf32(fmaxf(v.y + sB1[c4 + 1], 0.f));
            v.z = wmma::__float_to_tf32(fmaxf(v.z + sB1[c4 + 2], 0.f));
            v.w = wmma::__float_to_tf32(fmaxf(v.w + sB1[c4 + 3], 0.f));
            *p = v;
        }
    }
    __syncwarp();

    // ---- stage 2: t2_strip = C1_strip @ W2 ----
    {
        wmma::fragment<wmma::accumulator, 16, 16, 8, float> acc2[4];
        #pragma unroll
        for (int n = 0; n < 4; n++) wmma::fill_fragment(acc2[n], 0.f);

        #pragma unroll
        for (int k = 0; k < 16; k++) {
            wmma::load_matrix_sync(af, sC1 + warp * 16 * LDC1 + k * 8, LDC1);
            #pragma unroll
            for (int n = 0; n < 4; n++) {
                wmma::load_matrix_sync(bf, sW2 + (k * 8) * LDW2 + n * 16, LDW2);
                wmma::mma_sync(acc2[n], af, bf, acc2[n]);
            }
        }
        #pragma unroll
        for (int n = 0; n < 4; n++)
            wmma::store_matrix_sync(t2 + row0 * 64 + n * 16, acc2[n],
                                    64, wmma::mem_row_major);
    }
}

extern "C" void kernel_launch(void* const* d_in, const int* in_sizes, int n_in,
                              void* d_out, int out_size) {
    // Identify inputs by element count (robust to metadata ordering)
    const float* x  = nullptr; const void* ei = nullptr; const float* ew = nullptr;
    const float* W1 = nullptr; const float* b1 = nullptr;
    const float* W2 = nullptr; const float* b2 = nullptr;
    for (int i = 0; i < n_in; i++) {
        switch (in_sizes[i]) {
            case 12800000: x  = (const float*)d_in[i]; break;
            case 1200000:  ei = d_in[i];               break;
            case 600000:   ew = (const float*)d_in[i]; break;
            case 16384:    W1 = (const float*)d_in[i]; break;
            case 128:      b1 = (const float*)d_in[i]; break;
            case 8192:     W2 = (const float*)d_in[i]; break;
            case 64:       b2 = (const float*)d_in[i]; break;
            default: break;
        }
    }
    float* out = (float*)d_out;

    const int E = N_EDGES;

    float* aggx; cudaGetSymbolAddress((void**)&aggx, g_aggx_v);
    float* t2;   cudaGetSymbolAddress((void**)&t2,   g_t2_v);

    // fused GEMM needs > 48KB dynamic smem
    const int smem_bytes = (128 * LDW1 + 128 * LDW2 + 128 * LDC1 + 128) * 4;
    cudaFuncSetAttribute(fused_gemm, cudaFuncAttributeMaxDynamicSharedMemorySize,
                         smem_bytes);

    // 0) decode edge indices (dtype autodetect)
    decode_edges<<<(E + 255) / 256, 256>>>(ei, E);

    // 1) zero spmm-1 accumulator (incl. padding)
    {
        size_t n4 = (size_t)(N_NODES + PAD_ROWS) * IN_DIM / 4;
        zero_aggx<<<(int)((n4 + 255) / 256), 256>>>();
    }
    // 2) aggx[dst] += w * x[src]   (linearity: A(xW1) == (Ax)W1)
    {
        long long threads = (long long)E * (IN_DIM / 4);
        spmm_scatter<IN_DIM><<<(int)((threads + 255) / 256), 256>>>(ew, x, aggx, E);
    }
    // 3) t2 = relu(aggx @ W1 + b1) @ W2   (fused, tf32 tensor cores)
    {
        const int blocks = (N_NODES + 127) / 128;  // 782, padding covers the tail
        fused_gemm<<<blocks, 256, smem_bytes>>>(aggx, W1, b1, W2, t2);
    }
    // 4) out = b2 (broadcast init)
    {
        size_t n = (size_t)N_NODES * OUT_DIM;
        init_out<<<(int)((n + 255) / 256), 256>>>(out, b2);
    }
    // 5) out[dst] += w * t2[src]
    {
        long long threads = (long long)E * (OUT_DIM / 4);
        spmm_scatter<OUT_DIM><<<(int)((threads + 255) / 256), 256>>>(ew, t2, out, E);
    }
}

// round 7
// speedup vs baseline: 1.3060x; 1.0089x over previous
#include <cuda_runtime.h>
#include <cuda_bf16.h>
#include <mma.h>
#include <cstdint>

using namespace nvcuda;

// Problem constants (match reference setup_inputs)
#define N_NODES 100000
#define N_EDGES 600000
#define IN_DIM  128
#define OUT_DIM 64
#define PAD_ROWS 128   // tile padding so the fused GEMM needs no row predication

// -------- device-global scratch (no allocations allowed) --------
__device__ float4 g_aggx_v[(size_t)(N_NODES + PAD_ROWS) * IN_DIM / 4];  // A @ x
__device__ float4 g_t2_v[(size_t)(N_NODES + PAD_ROWS) * OUT_DIM / 4];   // relu(..)@W2
__device__ int    g_src[N_EDGES];
__device__ int    g_dst[N_EDGES];
__device__ float  g_w1t[IN_DIM * IN_DIM];    // W1 pre-rounded to tf32
__device__ float  g_w2t[IN_DIM * OUT_DIM];   // W2 pre-rounded to tf32

// -------- edge-index decode: auto-detect int32 vs int64 --------
__device__ __forceinline__ bool ei_is_int64(const void* p) {
    const long long* q = (const long long*)p;
    #pragma unroll
    for (int i = 0; i < 4; i++) {
        long long v = q[i];
        if (v < 0 || v >= N_NODES) return false;
    }
    return true;
}

__global__ __launch_bounds__(256) void decode_edges(const void* __restrict__ ei, int E) {
    int e = blockIdx.x * blockDim.x + threadIdx.x;
    if (e >= E) return;
    long long s, d;
    if (ei_is_int64(ei)) {
        const long long* q = (const long long*)ei;
        s = q[e]; d = q[(size_t)E + e];
    } else {
        const int* q = (const int*)ei;
        s = q[e]; d = q[(size_t)E + e];
    }
    if (s < 0 || s >= N_NODES) s = 0;
    if (d < 0 || d >= N_NODES) d = 0;
    g_src[e] = (int)s;
    g_dst[e] = (int)d;
}

// -------- pre-round weights to tf32 (one small launch) --------
__global__ __launch_bounds__(256) void conv_weights(const float* __restrict__ W1g,
                                                    const float* __restrict__ W2g) {
    int i = blockIdx.x * blockDim.x + threadIdx.x;
    if (i < IN_DIM * IN_DIM)  g_w1t[i] = wmma::__float_to_tf32(W1g[i]);
    if (i < IN_DIM * OUT_DIM) g_w2t[i] = wmma::__float_to_tf32(W2g[i]);
}

// -------- zero the spmm-1 accumulator (incl. padding) --------
__global__ __launch_bounds__(256) void zero_aggx() {
    size_t i = (size_t)blockIdx.x * blockDim.x + threadIdx.x;
    size_t n4 = (size_t)(N_NODES + PAD_ROWS) * IN_DIM / 4;
    if (i < n4) g_aggx_v[i] = make_float4(0.f, 0.f, 0.f, 0.f);
}

// -------- out[n][d] = b2[d]  (accumulator init for layer-2 spmm) --------
__global__ __launch_bounds__(256) void init_out(float* __restrict__ out,
                                                const float* __restrict__ b2) {
    size_t i = (size_t)blockIdx.x * blockDim.x + threadIdx.x;
    if (i < (size_t)N_NODES * OUT_DIM) {
        out[i] = b2[i & (OUT_DIM - 1)];
    }
}

// -------- SpMM scatter: acc[dst] += w_e * feat[src], D floats per edge --------
template<int D>
__global__ __launch_bounds__(256) void spmm_scatter(const float* __restrict__ ew,
                                                    const float* __restrict__ feat,
                                                    float* __restrict__ acc,
                                                    int E) {
    constexpr int L = D / 4;  // threads per edge: 32 (D=128) or 16 (D=64)
    const long long tid = (long long)blockIdx.x * blockDim.x + threadIdx.x;
    const int e = (int)(tid / L);
    const int lane = (int)(tid % L);
    if (e >= E) return;

    const int s = g_src[e];
    const int d = g_dst[e];
    const float w = ew[e];

    const float4 v = __ldg(((const float4*)(feat + (size_t)s * D)) + lane);
    float4* p = ((float4*)(acc + (size_t)d * D)) + lane;

    asm volatile("red.global.add.v4.f32 [%0], {%1, %2, %3, %4};"
                 :: "l"(p), "f"(v.x * w), "f"(v.y * w), "f"(v.z * w), "f"(v.w * w)
                 : "memory");
}

// -------- fused tf32 tensor-core GEMM: t2 = relu(Aggx @ W1 + b1) @ W2 --------
// Block: 128 rows, 256 threads (8 warps). Each warp owns a 16-row strip.
// Weights are read as matrix_b fragments DIRECTLY from global (L2-resident,
// pre-rounded to tf32) — smem holds only the per-warp C1 strips + bias, so
// ~70 KB/block -> 3 blocks/SM instead of 1.
#define LDC1 136

__global__ __launch_bounds__(256) void fused_gemm(const float* __restrict__ A,
                                                  const float* __restrict__ b1g,
                                                  float* __restrict__ t2) {
    extern __shared__ float smem[];
    float* sC1 = smem;                 // 128 x LDC1 (8 warp strips of 16 rows)
    float* sB1 = sC1 + 128 * LDC1;     // 128

    const int t = threadIdx.x;
    if (t < 128) sB1[t] = b1g[t];
    __syncthreads();

    const int warp = t >> 5;
    const int lane = t & 31;
    const size_t row0 = (size_t)blockIdx.x * 128 + warp * 16;
    float* myC1 = sC1 + warp * 16 * LDC1;

    wmma::fragment<wmma::matrix_a, 16, 16, 8, wmma::precision::tf32, wmma::row_major> af;
    wmma::fragment<wmma::matrix_b, 16, 16, 8, wmma::precision::tf32, wmma::row_major> bf;

    // ---- stage 1: C1 = A_strip @ W1 (W1 fragments straight from L2) ----
    {
        wmma::fragment<wmma::accumulator, 16, 16, 8, float> acc[8];
        #pragma unroll
        for (int n = 0; n < 8; n++) wmma::fill_fragment(acc[n], 0.f);

        #pragma unroll
        for (int k = 0; k < 16; k++) {
            wmma::load_matrix_sync(af, A + row0 * 128 + k * 8, 128);
            #pragma unroll
            for (int i = 0; i < af.num_elements; i++)
                af.x[i] = wmma::__float_to_tf32(af.x[i]);
            #pragma unroll
            for (int n = 0; n < 8; n++) {
                wmma::load_matrix_sync(bf, g_w1t + (k * 8) * 128 + n * 16, 128);
                wmma::mma_sync(acc[n], af, bf, acc[n]);
            }
        }
        #pragma unroll
        for (int n = 0; n < 8; n++)
            wmma::store_matrix_sync(myC1 + n * 16, acc[n], LDC1, wmma::mem_row_major);
    }
    __syncwarp();

    // ---- bias + relu + tf32-round on this warp's strip ----
    {
        for (int i = lane; i < 16 * 32; i += 32) {  // 16 rows x 32 float4
            const int r = i >> 5;
            const int c4 = (i & 31) * 4;
            float4* p = (float4*)(myC1 + r * LDC1 + c4);
            float4 v = *p;
            v.x = wmma::__float_to_tf32(fmaxf(v.x + sB1[c4 + 0], 0.f));
            v.y = wmma::__float_to_tf32(fmaxf(v.y + sB1[c4 + 1], 0.f));
            v.z = wmma::__float_to_tf32(fmaxf(v.z + sB1[c4 + 2], 0.f));
            v.w = wmma::__float_to_tf32(fmaxf(v.w + sB1[c4 + 3], 0.f));
            *p = v;
        }
    }
    __syncwarp();

    // ---- stage 2: t2_strip = C1_strip @ W2 (W2 fragments from L2) ----
    {
        wmma::fragment<wmma::accumulator, 16, 16, 8, float> acc2[4];
        #pragma unroll
        for (int n = 0; n < 4; n++) wmma::fill_fragment(acc2[n], 0.f);

        #pragma unroll
        for (int k = 0; k < 16; k++) {
            wmma::load_matrix_sync(af, myC1 + k * 8, LDC1);
            #pragma unroll
            for (int n = 0; n < 4; n++) {
                wmma::load_matrix_sync(bf, g_w2t + (k * 8) * 64 + n * 16, 64);
                wmma::mma_sync(acc2[n], af, bf, acc2[n]);
            }
        }
        #pragma unroll
        for (int n = 0; n < 4; n++)
            wmma::store_matrix_sync(t2 + row0 * 64 + n * 16, acc2[n],
                                    64, wmma::mem_row_major);
    }
}

extern "C" void kernel_launch(void* const* d_in, const int* in_sizes, int n_in,
                              void* d_out, int out_size) {
    // Identify inputs by element count (robust to metadata ordering)
    const float* x  = nullptr; const void* ei = nullptr; const float* ew = nullptr;
    const float* W1 = nullptr; const float* b1 = nullptr;
    const float* W2 = nullptr; const float* b2 = nullptr;
    for (int i = 0; i < n_in; i++) {
        switch (in_sizes[i]) {
            case 12800000: x  = (const float*)d_in[i]; break;
            case 1200000:  ei = d_in[i];               break;
            case 600000:   ew = (const float*)d_in[i]; break;
            case 16384:    W1 = (const float*)d_in[i]; break;
            case 128:      b1 = (const float*)d_in[i]; break;
            case 8192:     W2 = (const float*)d_in[i]; break;
            case 64:       b2 = (const float*)d_in[i]; break;
            default: break;
        }
    }
    float* out = (float*)d_out;

    const int E = N_EDGES;

    float* aggx; cudaGetSymbolAddress((void**)&aggx, g_aggx_v);
    float* t2;   cudaGetSymbolAddress((void**)&t2,   g_t2_v);

    // smem: C1 strips + bias only (~70 KB) -> 3 blocks/SM
    const int smem_bytes = (128 * LDC1 + 128) * 4;
    cudaFuncSetAttribute(fused_gemm, cudaFuncAttributeMaxDynamicSharedMemorySize,
                         smem_bytes);

    // 0) decode edge indices + pre-round weights to tf32
    decode_edges<<<(E + 255) / 256, 256>>>(ei, E);
    conv_weights<<<(IN_DIM * IN_DIM + 255) / 256, 256>>>(W1, W2);

    // 1) zero spmm-1 accumulator (incl. padding)
    {
        size_t n4 = (size_t)(N_NODES + PAD_ROWS) * IN_DIM / 4;
        zero_aggx<<<(int)((n4 + 255) / 256), 256>>>();
    }
    // 2) aggx[dst] += w * x[src]   (linearity: A(xW1) == (Ax)W1)
    {
        long long threads = (long long)E * (IN_DIM / 4);
        spmm_scatter<IN_DIM><<<(int)((threads + 255) / 256), 256>>>(ew, x, aggx, E);
    }
    // 3) t2 = relu(aggx @ W1 + b1) @ W2   (fused, tf32 tensor cores)
    {
        const int blocks = (N_NODES + 127) / 128;  // 782, padding covers the tail
        fused_gemm<<<blocks, 256, smem_bytes>>>(aggx, b1, t2);
    }
    // 4) out = b2 (broadcast init)
    {
        size_t n = (size_t)N_NODES * OUT_DIM;
        init_out<<<(int)((n + 255) / 256), 256>>>(out, b2);
    }
    // 5) out[dst] += w * t2[src]
    {
        long long threads = (long long)E * (OUT_DIM / 4);
        spmm_scatter<OUT_DIM><<<(int)((threads + 255) / 256), 256>>>(ew, t2, out, E);
    }
}

// round 9
// speedup vs baseline: 1.6046x; 1.2286x over previous
#include <cuda_runtime.h>
#include <cuda_bf16.h>
#include <mma.h>
#include <cstdint>

using namespace nvcuda;

// Problem constants (match reference setup_inputs)
#define N_NODES 100000
#define N_EDGES 600000
#define IN_DIM  128
#define OUT_DIM 64
#define PAD_ROWS 128
#define SCAN_BLOCKS ((N_NODES + 255) / 256)   // 391

// -------- device-global scratch (no allocations allowed) --------
__device__ float4 g_aggx_v[(size_t)(N_NODES + PAD_ROWS) * IN_DIM / 4];  // A @ x
__device__ float4 g_c1_v[(size_t)(N_NODES + PAD_ROWS) * IN_DIM / 4];    // relu(.@W1+b1)
__device__ float4 g_t2_v[(size_t)(N_NODES + PAD_ROWS) * OUT_DIM / 4];   // .@W2
__device__ int    g_src[N_EDGES];
__device__ int    g_dst[N_EDGES];
__device__ float  g_w1t[IN_DIM * IN_DIM];    // W1 tf32-rounded
__device__ float  g_w2t[IN_DIM * OUT_DIM];   // W2 tf32-rounded
// CSR (bucketed by dst)
__device__ int    g_deg[N_NODES];
__device__ int    g_fill[N_NODES];
__device__ int    g_ptr[N_NODES + 1];
__device__ int    g_blk[SCAN_BLOCKS];
__device__ int    g_csr_src[N_EDGES];
__device__ float  g_csr_w[N_EDGES];

// -------- zero per-call CSR counters --------
__global__ __launch_bounds__(256) void zero_counts() {
    int i = blockIdx.x * blockDim.x + threadIdx.x;
    if (i < N_NODES) { g_deg[i] = 0; g_fill[i] = 0; }
}

// -------- edge-index decode (int32/int64 autodetect) + degree count --------
__device__ __forceinline__ bool ei_is_int64(const void* p) {
    const long long* q = (const long long*)p;
    #pragma unroll
    for (int i = 0; i < 4; i++) {
        long long v = q[i];
        if (v < 0 || v >= N_NODES) return false;
    }
    return true;
}

__global__ __launch_bounds__(256) void decode_edges(const void* __restrict__ ei, int E) {
    int e = blockIdx.x * blockDim.x + threadIdx.x;
    if (e >= E) return;
    long long s, d;
    if (ei_is_int64(ei)) {
        const long long* q = (const long long*)ei;
        s = q[e]; d = q[(size_t)E + e];
    } else {
        const int* q = (const int*)ei;
        s = q[e]; d = q[(size_t)E + e];
    }
    if (s < 0 || s >= N_NODES) s = 0;
    if (d < 0 || d >= N_NODES) d = 0;
    g_src[e] = (int)s;
    g_dst[e] = (int)d;
    atomicAdd(&g_deg[(int)d], 1);
}

// -------- exclusive scan of g_deg -> g_ptr (3-kernel hierarchy) --------
__global__ __launch_bounds__(256) void scan1() {
    __shared__ int s[256];
    const int tid = threadIdx.x;
    const int i = blockIdx.x * 256 + tid;
    int v = (i < N_NODES) ? g_deg[i] : 0;
    s[tid] = v;
    __syncthreads();
    for (int off = 1; off < 256; off <<= 1) {
        int t = (tid >= off) ? s[tid - off] : 0;
        __syncthreads();
        s[tid] += t;
        __syncthreads();
    }
    if (i < N_NODES) g_ptr[i] = s[tid] - v;            // block-local exclusive
    if (tid == 255) g_blk[blockIdx.x] = s[255];        // block total
}

__global__ __launch_bounds__(512) void scan2() {       // 1 block over block sums
    __shared__ int s[512];
    const int tid = threadIdx.x;
    int v = (tid < SCAN_BLOCKS) ? g_blk[tid] : 0;
    s[tid] = v;
    __syncthreads();
    for (int off = 1; off < 512; off <<= 1) {
        int t = (tid >= off) ? s[tid - off] : 0;
        __syncthreads();
        s[tid] += t;
        __syncthreads();
    }
    if (tid < SCAN_BLOCKS) g_blk[tid] = s[tid] - v;    // exclusive
}

__global__ __launch_bounds__(256) void scan3() {
    int i = blockIdx.x * blockDim.x + threadIdx.x;
    if (i < N_NODES) g_ptr[i] += g_blk[i >> 8];
    if (i == 0) g_ptr[N_NODES] = N_EDGES;
}

// -------- bucket-fill CSR --------
__global__ __launch_bounds__(256) void fill_csr(const float* __restrict__ ew, int E) {
    int e = blockIdx.x * blockDim.x + threadIdx.x;
    if (e >= E) return;
    const int d = g_dst[e];
    const int pos = g_ptr[d] + atomicAdd(&g_fill[d], 1);
    g_csr_src[pos] = g_src[e];
    g_csr_w[pos]   = ew[e];
}

// -------- gather SpMM, layer 1: aggx[n] = sum_e w_e * x[src_e]  (warp/node) --------
__global__ __launch_bounds__(256) void gather1(const float* __restrict__ x,
                                               float* __restrict__ aggx) {
    const int w = (blockIdx.x * 256 + threadIdx.x) >> 5;
    const int lane = threadIdx.x & 31;
    if (w >= N_NODES) return;
    const int beg = g_ptr[w], end = g_ptr[w + 1];
    float4 acc = make_float4(0.f, 0.f, 0.f, 0.f);
    for (int e = beg; e < end; e++) {
        const int s = g_csr_src[e];
        const float wt = g_csr_w[e];
        const float4 v = __ldg(((const float4*)(x + (size_t)s * IN_DIM)) + lane);
        acc.x += wt * v.x; acc.y += wt * v.y; acc.z += wt * v.z; acc.w += wt * v.w;
    }
    ((float4*)(aggx + (size_t)w * IN_DIM))[lane] = acc;
}

// -------- gather SpMM, layer 2: out[n] = b2 + sum w_e * t2[src]  (halfwarp/node) --------
__global__ __launch_bounds__(256) void gather2(const float* __restrict__ t2,
                                               const float* __restrict__ b2,
                                               float* __restrict__ out) {
    const int n = (blockIdx.x * 256 + threadIdx.x) >> 4;
    const int lane = threadIdx.x & 15;
    if (n >= N_NODES) return;
    const int beg = g_ptr[n], end = g_ptr[n + 1];
    float4 acc = __ldg(((const float4*)b2) + lane);
    for (int e = beg; e < end; e++) {
        const int s = g_csr_src[e];
        const float wt = g_csr_w[e];
        const float4 v = __ldg(((const float4*)(t2 + (size_t)s * OUT_DIM)) + lane);
        acc.x += wt * v.x; acc.y += wt * v.y; acc.z += wt * v.z; acc.w += wt * v.w;
    }
    ((float4*)(out + (size_t)n * OUT_DIM))[lane] = acc;
}

// -------- pre-round weights to tf32 --------
__global__ __launch_bounds__(256) void conv_weights(const float* __restrict__ W1g,
                                                    const float* __restrict__ W2g) {
    int i = blockIdx.x * blockDim.x + threadIdx.x;
    if (i < IN_DIM * IN_DIM)  g_w1t[i] = wmma::__float_to_tf32(W1g[i]);
    if (i < IN_DIM * OUT_DIM) g_w2t[i] = wmma::__float_to_tf32(W2g[i]);
}

// -------- gemm1: C1 = tf32_round(relu(aggx @ W1 + b1)) --------
// 256 thr / 8 warps / 128 rows. W1 in smem (67.7KB -> 3 blocks/SM).
// Epilogue reuses the (dead) W1 smem region as per-warp staging.
#define LDW1 132

__global__ __launch_bounds__(256) void gemm1(const float* __restrict__ A,
                                             const float* __restrict__ b1g,
                                             float* __restrict__ C1) {
    extern __shared__ float smem[];          // 128*LDW1 + 128 floats
    float* sW1 = smem;
    float* sB1 = smem + 128 * LDW1;

    const int t = threadIdx.x;
    for (int i = t; i < 128 * 128; i += 256)
        sW1[(i >> 7) * LDW1 + (i & 127)] = g_w1t[i];
    if (t < 128) sB1[t] = b1g[t];
    __syncthreads();

    const int warp = t >> 5;
    const int lane = t & 31;
    const size_t row0 = (size_t)blockIdx.x * 128 + warp * 16;

    wmma::fragment<wmma::matrix_a, 16, 16, 8, wmma::precision::tf32, wmma::row_major> af;
    wmma::fragment<wmma::matrix_b, 16, 16, 8, wmma::precision::tf32, wmma::row_major> bf;
    wmma::fragment<wmma::accumulator, 16, 16, 8, float> acc[8];
    #pragma unroll
    for (int n = 0; n < 8; n++) wmma::fill_fragment(acc[n], 0.f);

    #pragma unroll
    for (int k = 0; k < 16; k++) {
        wmma::load_matrix_sync(af, A + row0 * 128 + k * 8, 128);
        #pragma unroll
        for (int i = 0; i < af.num_elements; i++)
            af.x[i] = wmma::__float_to_tf32(af.x[i]);
        #pragma unroll
        for (int n = 0; n < 8; n++) {
            wmma::load_matrix_sync(bf, sW1 + (k * 8) * LDW1 + n * 16, LDW1);
            wmma::mma_sync(acc[n], af, bf, acc[n]);
        }
    }

    __syncthreads();   // everyone done reading W1 -> reuse as staging
    float* stg = sW1 + warp * 16 * LDW1;
    #pragma unroll
    for (int n = 0; n < 8; n++)
        wmma::store_matrix_sync(stg + n * 16, acc[n], LDW1, wmma::mem_row_major);
    __syncwarp();

    for (int i = lane; i < 16 * 32; i += 32) {   // 16 rows x 32 float4
        const int r = i >> 5;
        const int c4 = (i & 31) * 4;
        const float* p = stg + r * LDW1 + c4;
        float4 v = make_float4(p[0], p[1], p[2], p[3]);
        v.x = wmma::__float_to_tf32(fmaxf(v.x + sB1[c4 + 0], 0.f));
        v.y = wmma::__float_to_tf32(fmaxf(v.y + sB1[c4 + 1], 0.f));
        v.z = wmma::__float_to_tf32(fmaxf(v.z + sB1[c4 + 2], 0.f));
        v.w = wmma::__float_to_tf32(fmaxf(v.w + sB1[c4 + 3], 0.f));
        *(float4*)(C1 + (row0 + r) * 128 + c4) = v;
    }
}

// -------- gemm2: t2 = C1 @ W2 (C1 already tf32) --------
// 256 thr / 8 warps / 128 rows. W2 in smem (36.9KB -> 6 blocks/SM).
#define LDW2 72

__global__ __launch_bounds__(256) void gemm2(const float* __restrict__ C1,
                                             float* __restrict__ t2) {
    __shared__ float sW2[128 * LDW2];
    const int t = threadIdx.x;
    for (int i = t; i < 128 * 64; i += 256)
        sW2[(i >> 6) * LDW2 + (i & 63)] = g_w2t[i];
    __syncthreads();

    const int warp = t >> 5;
    const size_t row0 = (size_t)blockIdx.x * 128 + warp * 16;

    wmma::fragment<wmma::matrix_a, 16, 16, 8, wmma::precision::tf32, wmma::row_major> af;
    wmma::fragment<wmma::matrix_b, 16, 16, 8, wmma::precision::tf32, wmma::row_major> bf;
    wmma::fragment<wmma::accumulator, 16, 16, 8, float> acc[4];
    #pragma unroll
    for (int n = 0; n < 4; n++) wmma::fill_fragment(acc[n], 0.f);

    #pragma unroll
    for (int k = 0; k < 16; k++) {
        wmma::load_matrix_sync(af, C1 + row0 * 128 + k * 8, 128);
        #pragma unroll
        for (int n = 0; n < 4; n++) {
            wmma::load_matrix_sync(bf, sW2 + (k * 8) * LDW2 + n * 16, LDW2);
            wmma::mma_sync(acc[n], af, bf, acc[n]);
        }
    }
    #pragma unroll
    for (int n = 0; n < 4; n++)
        wmma::store_matrix_sync(t2 + row0 * 64 + n * 16, acc[n],
                                64, wmma::mem_row_major);
}

extern "C" void kernel_launch(void* const* d_in, const int* in_sizes, int n_in,
                              void* d_out, int out_size) {
    // Identify inputs by element count (robust to metadata ordering)
    const float* x  = nullptr; const void* ei = nullptr; const float* ew = nullptr;
    const float* W1 = nullptr; const float* b1 = nullptr;
    const float* W2 = nullptr; const float* b2 = nullptr;
    for (int i = 0; i < n_in; i++) {
        switch (in_sizes[i]) {
            case 12800000: x  = (const float*)d_in[i]; break;
            case 1200000:  ei = d_in[i];               break;
            case 600000:   ew = (const float*)d_in[i]; break;
            case 16384:    W1 = (const float*)d_in[i]; break;
            case 128:      b1 = (const float*)d_in[i]; break;
            case 8192:     W2 = (const float*)d_in[i]; break;
            case 64:       b2 = (const float*)d_in[i]; break;
            default: break;
        }
    }
    float* out = (float*)d_out;
    const int E = N_EDGES;

    float* aggx; cudaGetSymbolAddress((void**)&aggx, g_aggx_v);
    float* c1;   cudaGetSymbolAddress((void**)&c1,   g_c1_v);
    float* t2;   cudaGetSymbolAddress((void**)&t2,   g_t2_v);

    const int smem1 = (128 * LDW1 + 128) * 4;   // 67.7 KB
    cudaFuncSetAttribute(gemm1, cudaFuncAttributeMaxDynamicSharedMemorySize, smem1);

    // --- CSR build ---
    zero_counts<<<SCAN_BLOCKS, 256>>>();
    decode_edges<<<(E + 255) / 256, 256>>>(ei, E);
    conv_weights<<<(IN_DIM * IN_DIM + 255) / 256, 256>>>(W1, W2);
    scan1<<<SCAN_BLOCKS, 256>>>();
    scan2<<<1, 512>>>();
    scan3<<<SCAN_BLOCKS, 256>>>();
    fill_csr<<<(E + 255) / 256, 256>>>(ew, E);

    // --- layer 1: aggx = A @ x  (pull-mode gather, warp per node) ---
    gather1<<<(N_NODES * 32 + 255) / 256, 256>>>(x, aggx);

    // --- C1 = tf32(relu(aggx @ W1 + b1)) ; t2 = C1 @ W2 ---
    const int gblocks = (N_NODES + 127) / 128;  // 782 (padding covers tail rows)
    gemm1<<<gblocks, 256, smem1>>>(aggx, b1, c1);
    gemm2<<<gblocks, 256>>>(c1, t2);

    // --- layer 2: out = b2 + A @ t2  (half-warp per node) ---
    gather2<<<(N_NODES * 16 + 255) / 256, 256>>>(t2, b2, out);
}